// round 17
// baseline (speedup 1.0000x reference)
// r17: hgemm 3-stage ring pipeline, single barrier per K-chunk (rest = r15b)
#include <cuda_runtime.h>
#include <cuda_fp16.h>
#include <math.h>
#include <stdint.h>

#define Bq   8
#define Sq   1024
#define Dq   1024
#define Hq   16
#define DKq  64
#define DFFq 4096
#define MROWS (Bq * Sq)
#define NQKV 3072

typedef __half h16;

// ---------------- scratch ----------------
__device__ float g_tmp[MROWS * Dq];
__device__ float g_x1 [MROWS * Dq];
__device__ h16 g_qkv[MROWS * NQKV];
__device__ h16 g_xh [MROWS * Dq];
__device__ h16 g_ah [MROWS * Dq];
__device__ h16 g_x1h[MROWS * Dq];
__device__ h16 g_fh [MROWS * DFFq];
__device__ h16 g_wcat[NQKV * Dq];
__device__ float g_bcat[NQKV];
__device__ h16 g_woh[Dq * Dq];
__device__ h16 g_w1h[Dq * DFFq];
__device__ h16 g_w2h[DFFq * Dq];

// ---------------- helpers ----------------
__device__ __forceinline__ uint32_t smem_u32(const void* p) {
    uint32_t a;
    asm("{ .reg .u64 t; cvta.to.shared.u64 t, %1; cvt.u32.u64 %0, t; }" : "=r"(a) : "l"(p));
    return a;
}
__device__ __forceinline__ void cpa16(uint32_t s, const void* g) {
    asm volatile("cp.async.cg.shared.global [%0], [%1], 16;" :: "r"(s), "l"(g));
}
#define CP_COMMIT() asm volatile("cp.async.commit_group;" ::: "memory")
#define CP_WAIT1()  asm volatile("cp.async.wait_group 1;" ::: "memory")
#define CP_WAIT0()  asm volatile("cp.async.wait_group 0;" ::: "memory")
#define LDMX4(r0,r1,r2,r3,addr)                                               \
    asm volatile("ldmatrix.sync.aligned.m8n8.x4.shared.b16 {%0,%1,%2,%3},[%4];" \
        : "=r"(r0), "=r"(r1), "=r"(r2), "=r"(r3) : "r"(addr))
#define LDMX4T(r0,r1,r2,r3,addr)                                              \
    asm volatile("ldmatrix.sync.aligned.m8n8.x4.trans.shared.b16 {%0,%1,%2,%3},[%4];" \
        : "=r"(r0), "=r"(r1), "=r"(r2), "=r"(r3) : "r"(addr))
#define HMMA(d,a,b)                                                           \
    asm volatile("mma.sync.aligned.m16n8k16.row.col.f32.f16.f16.f32 "         \
        "{%0,%1,%2,%3},{%4,%5,%6,%7},{%8,%9},{%0,%1,%2,%3};"                  \
        : "+f"((d)[0]), "+f"((d)[1]), "+f"((d)[2]), "+f"((d)[3])              \
        : "r"((a)[0]), "r"((a)[1]), "r"((a)[2]), "r"((a)[3]),                 \
          "r"((b)[0]), "r"((b)[1]))

// ---------------- fp16 HMMA GEMM: C = Ah @ Bh^T + bias ---------------------
// 1-term, BM=128 BN=256 BK=64, 256 thr, warp tile 64x64, 3-stage ring.
#define BM 128
#define BN 256
#define BK 64
#define OFF_A 0
#define OFF_B 16384
#define BUFB  49152
#define SMEM_REQ (3 * BUFB)            // 147456

__global__ __launch_bounds__(256) void hgemm(
    const h16* __restrict__ Ahb, const h16* __restrict__ Bhb,
    const float* __restrict__ bias, float* __restrict__ C,
    h16* __restrict__ Ch,
    int M, int N, int K, int doRelu)
{
    extern __shared__ char smem[];
    const uint32_t sb = smem_u32(smem);
    const int tid  = threadIdx.x;
    const int warp = tid >> 5, lane = tid & 31;
    const int bm = blockIdx.y * BM, bn = blockIdx.x * BN;
    const int m0w = (warp & 1) * 64, n0w = (warp >> 1) * 64;

    const int rL = tid >> 3, cL = tid & 7;
    const uint32_t sRowOff = (uint32_t)rL * 128 + (((uint32_t)(cL ^ (rL & 7))) << 4);
    const h16* gA = Ahb + (size_t)(bm + rL) * K + cL * 8;
    const h16* gB = Bhb + (size_t)(bn + rL) * K + cL * 8;
    const size_t rstep = (size_t)32 * K;

    float acc[4][8][4];
#pragma unroll
    for (int i = 0; i < 4; i++)
#pragma unroll
        for (int j = 0; j < 8; j++)
#pragma unroll
            for (int r = 0; r < 4; r++) acc[i][j][r] = 0.f;

    const int arow0 = m0w + (lane & 15);
    const int akc   = lane >> 4;
    const int brow0 = n0w + ((lane >> 4) << 3) + (lane & 7);
    const int bkc   = (lane >> 3) & 1;

    auto LOAD = [&](int c, int buf) {
        const uint32_t s = sb + (uint32_t)buf * BUFB;
        const size_t k0 = (size_t)c * BK;
#pragma unroll
        for (int i = 0; i < 4; i++) {
            const uint32_t so = sRowOff + (uint32_t)i * 4096;
            cpa16(s + OFF_A + so, gA + (size_t)i * rstep + k0);
        }
#pragma unroll
        for (int i = 0; i < 8; i++) {
            const uint32_t so = sRowOff + (uint32_t)i * 4096;
            cpa16(s + OFF_B + so, gB + (size_t)i * rstep + k0);
        }
    };

    auto COMPUTE = [&](int buf) {
        const uint32_t s = sb + (uint32_t)buf * BUFB;
#pragma unroll
        for (int ks = 0; ks < 4; ks++) {
            uint32_t bh[8][2];
#pragma unroll
            for (int bt = 0; bt < 4; bt++) {
                const int row = brow0 + bt * 16;
                const int kc  = ks * 2 + bkc;
                const uint32_t off = (uint32_t)row * 128 + (((uint32_t)(kc ^ (row & 7))) << 4);
                LDMX4(bh[2*bt][0], bh[2*bt][1], bh[2*bt+1][0], bh[2*bt+1][1], s + OFF_B + off);
            }
#pragma unroll
            for (int mt = 0; mt < 4; mt++) {
                const int row = arow0 + mt * 16;
                const int kc  = ks * 2 + akc;
                const uint32_t off = (uint32_t)row * 128 + (((uint32_t)(kc ^ (row & 7))) << 4);
                uint32_t a[4];
                LDMX4(a[0], a[1], a[2], a[3], s + OFF_A + off);
#pragma unroll
                for (int nt = 0; nt < 8; nt++) HMMA(acc[mt][nt], a, bh[nt]);
            }
        }
    };

    const int chunks = K / BK;
    LOAD(0, 0);
    CP_COMMIT();
    if (chunks > 1) { LOAD(1, 1); CP_COMMIT(); }
#pragma unroll 1
    for (int c = 0; c < chunks; c++) {
        CP_WAIT1();             // chunk c landed (≤1 younger group pending)
        __syncthreads();        // all threads past compute(c-1); chunk c visible
        if (c + 2 < chunks) {   // refill buffer (c-1)%3 — safe after the sync
            LOAD(c + 2, (c + 2) % 3);
            CP_COMMIT();
        }
        COMPUTE(c % 3);
    }

#pragma unroll
    for (int mt = 0; mt < 4; mt++) {
        const int mr = bm + m0w + mt * 16 + (lane >> 2);
#pragma unroll
        for (int nt = 0; nt < 8; nt++) {
            const int col = bn + n0w + nt * 8 + 2 * (lane & 3);
            const float b0 = bias[col], b1 = bias[col + 1];
            float v0 = acc[mt][nt][0] + b0, v1 = acc[mt][nt][1] + b1;
            float v2 = acc[mt][nt][2] + b0, v3 = acc[mt][nt][3] + b1;
            if (doRelu) {
                v0 = fmaxf(v0, 0.f); v1 = fmaxf(v1, 0.f);
                v2 = fmaxf(v2, 0.f); v3 = fmaxf(v3, 0.f);
            }
            if (C) {
                *(float2*)(C + (size_t)mr * N + col)       = make_float2(v0, v1);
                *(float2*)(C + (size_t)(mr + 8) * N + col) = make_float2(v2, v3);
            }
            if (Ch) {
                *(__half2*)(Ch + (size_t)mr * N + col)       = __floats2half2_rn(v0, v1);
                *(__half2*)(Ch + (size_t)(mr + 8) * N + col) = __floats2half2_rn(v2, v3);
            }
        }
    }
}

// ---------------- pre-pass kernels ----------------
__global__ __launch_bounds__(256) void vround_kernel(
    const float* __restrict__ s, h16* __restrict__ h, int n)
{
    int i = (blockIdx.x * 256 + threadIdx.x) * 4;
    if (i >= n) return;
    float4 v = *(const float4*)(s + i);
    *(__half2*)(h+i)   = __floats2half2_rn(v.x, v.y);
    *(__half2*)(h+i+2) = __floats2half2_rn(v.z, v.w);
}

__global__ __launch_bounds__(256) void ttrans_kernel(
    const float* __restrict__ W, h16* __restrict__ Th, int K, int N)
{
    __shared__ float t[32][33];
    const int n0 = blockIdx.x * 32, k0 = blockIdx.y * 32;
    const int tx = threadIdx.x & 31, ty = threadIdx.x >> 5;
#pragma unroll
    for (int i = ty; i < 32; i += 8)
        t[i][tx] = W[(size_t)(k0 + i) * N + n0 + tx];
    __syncthreads();
#pragma unroll
    for (int i = ty; i < 32; i += 8)
        Th[(size_t)(n0 + i) * K + k0 + tx] = __float2half_rn(t[tx][i]);
}

__global__ __launch_bounds__(256) void bcat_kernel(
    const float* __restrict__ a, const float* __restrict__ b,
    const float* __restrict__ c, float* __restrict__ o)
{
    int i = blockIdx.x * 256 + threadIdx.x;
    if (i < 1024) o[i] = a[i];
    else if (i < 2048) o[i] = b[i - 1024];
    else if (i < 3072) o[i] = c[i - 2048];
}

// ---------------- HMMA flash attention: 128 q-rows/block, 8 warps ----------
__global__ __launch_bounds__(256) void attention_hmma(
    const h16* __restrict__ QKV, const int* __restrict__ mask,
    h16* __restrict__ OH)
{
    __shared__ h16 Qs[128 * 64];
    __shared__ h16 Ks[64 * 64];
    __shared__ h16 Vs[64 * 64];
    __shared__ int ms[64];

    const int b = blockIdx.z, h = blockIdx.y, qt = blockIdx.x;
    const int tid = threadIdx.x, warp = tid >> 5, lane = tid & 31;
    const uint32_t qsb = smem_u32(Qs), ksb = smem_u32(Ks), vsb = smem_u32(Vs);

    const int lrq = tid >> 1, lcq = (tid & 1) * 4;
    const int lrk = tid >> 2, lck = (tid & 3) * 2;

    const h16* qg  = QKV + (size_t)(b * Sq + qt * 128 + lrq) * NQKV + h * 64;
    const h16* kgb = QKV + (size_t)(b * Sq + lrk) * NQKV + 1024 + h * 64;
    const h16* vgb = QKV + (size_t)(b * Sq + lrk) * NQKV + 2048 + h * 64;

#pragma unroll
    for (int c = 0; c < 4; c++) {
        const int ch = lcq + c;
        const uint32_t sw = (uint32_t)lrq * 128 + (((uint32_t)(ch ^ (lrq & 7))) << 4);
        cpa16(qsb + sw, qg + ch * 8);
    }
#pragma unroll
    for (int c = 0; c < 2; c++) {
        const int ch = lck + c;
        const uint32_t sw = (uint32_t)lrk * 128 + (((uint32_t)(ch ^ (lrk & 7))) << 4);
        cpa16(ksb + sw, kgb + ch * 8);
        cpa16(vsb + sw, vgb + ch * 8);
    }
    if (tid < 64) ms[tid] = mask[b * Sq + tid];
    CP_COMMIT();
    CP_WAIT0();
    __syncthreads();

    uint32_t qf[4][4];
    {
        const int row = warp * 16 + (lane & 15);
        const int kb = lane >> 4;
#pragma unroll
        for (int kf = 0; kf < 4; kf++) {
            const int kc = kf * 2 + kb;
            const uint32_t off = (uint32_t)row * 128 + (((uint32_t)(kc ^ (row & 7))) << 4);
            LDMX4(qf[kf][0], qf[kf][1], qf[kf][2], qf[kf][3], qsb + off);
        }
    }

    float oacc[8][4];
#pragma unroll
    for (int t = 0; t < 8; t++)
#pragma unroll
        for (int r = 0; r < 4; r++) oacc[t][r] = 0.f;
    float lsum0 = 0.f, lsum1 = 0.f;

    const int sb_row = ((lane >> 4) << 3) + (lane & 7);
    const int sb_kc  = (lane >> 3) & 1;
    const int vrow   = ((lane >> 3) & 1) * 8 + (lane & 7);
    const int vchb   = lane >> 4;
    const int mcol   = 2 * (lane & 3);

#pragma unroll 1
    for (int c = 0; c < 16; c++) {
        float sacc[8][4];
#pragma unroll
        for (int t = 0; t < 8; t++)
#pragma unroll
            for (int r = 0; r < 4; r++) sacc[t][r] = 0.f;
#pragma unroll
        for (int jt = 0; jt < 4; jt++) {
            const int row = jt * 16 + sb_row;
#pragma unroll
            for (int kf = 0; kf < 4; kf++) {
                const int kc = kf * 2 + sb_kc;
                const uint32_t off = (uint32_t)row * 128 + (((uint32_t)(kc ^ (row & 7))) << 4);
                uint32_t bb[4];
                LDMX4(bb[0], bb[1], bb[2], bb[3], ksb + off);
                HMMA(sacc[2*jt],   qf[kf], (bb));
                HMMA(sacc[2*jt+1], qf[kf], (bb + 2));
            }
        }

        uint32_t pf[4][4];
#pragma unroll
        for (int t = 0; t < 8; t++) {
            const int col = t * 8 + mcol;
            const int m0 = ms[col], m1 = ms[col + 1];
            float p0 = m0 ? __expf(0.125f * sacc[t][0]) : 0.f;
            float p1 = m1 ? __expf(0.125f * sacc[t][1]) : 0.f;
            float p2 = m0 ? __expf(0.125f * sacc[t][2]) : 0.f;
            float p3 = m1 ? __expf(0.125f * sacc[t][3]) : 0.f;
            lsum0 += p0 + p1;
            lsum1 += p2 + p3;
            __half2 a01 = __floats2half2_rn(p0, p1);
            __half2 a23 = __floats2half2_rn(p2, p3);
            pf[t >> 1][(t & 1) * 2 + 0] = *(uint32_t*)&a01;
            pf[t >> 1][(t & 1) * 2 + 1] = *(uint32_t*)&a23;
        }

#pragma unroll
        for (int np = 0; np < 4; np++) {
            const int chunk = np * 2 + vchb;
#pragma unroll
            for (int kt = 0; kt < 4; kt++) {
                const int r = kt * 16 + vrow;
                const uint32_t off = (uint32_t)r * 128 + (((uint32_t)(chunk ^ (r & 7))) << 4);
                uint32_t vb[4];
                LDMX4T(vb[0], vb[1], vb[2], vb[3], vsb + off);
                HMMA(oacc[2*np],   pf[kt], (vb));
                HMMA(oacc[2*np+1], pf[kt], (vb + 2));
            }
        }

        if (c < 15) {
            __syncthreads();
            const size_t gofs = (size_t)(c + 1) * 64 * NQKV;
#pragma unroll
            for (int cc = 0; cc < 2; cc++) {
                const int ch = lck + cc;
                const uint32_t sw = (uint32_t)lrk * 128 + (((uint32_t)(ch ^ (lrk & 7))) << 4);
                cpa16(ksb + sw, kgb + gofs + ch * 8);
                cpa16(vsb + sw, vgb + gofs + ch * 8);
            }
            if (tid < 64) ms[tid] = mask[b * Sq + (c + 1) * 64 + tid];
            CP_COMMIT();
            CP_WAIT0();
            __syncthreads();
        }
    }

    lsum0 += __shfl_xor_sync(0xffffffffu, lsum0, 1);
    lsum0 += __shfl_xor_sync(0xffffffffu, lsum0, 2);
    lsum1 += __shfl_xor_sync(0xffffffffu, lsum1, 1);
    lsum1 += __shfl_xor_sync(0xffffffffu, lsum1, 2);
    const float inv0 = 1.f / lsum0, inv1 = 1.f / lsum1;

    const int qr0 = qt * 128 + warp * 16 + (lane >> 2);
    const size_t gr0 = (size_t)(b * Sq + qr0) * Dq;
    const size_t gr1 = gr0 + (size_t)8 * Dq;
#pragma unroll
    for (int t = 0; t < 8; t++) {
        const int col = h * 64 + t * 8 + mcol;
        *(__half2*)(OH + gr0 + col) = __floats2half2_rn(oacc[t][0] * inv0, oacc[t][1] * inv0);
        *(__half2*)(OH + gr1 + col) = __floats2half2_rn(oacc[t][2] * inv1, oacc[t][3] * inv1);
    }
}

// ---------------- residual + LayerNorm (opt fp16 out) ----------------
__global__ __launch_bounds__(256) void residual_ln(
    const float* __restrict__ X, const float* __restrict__ Y,
    const float* __restrict__ Aw, const float* __restrict__ Bw,
    float* __restrict__ out, h16* __restrict__ oh)
{
    const int row = blockIdx.x, tid = threadIdx.x;
    const size_t base = (size_t)row * Dq + tid * 4;
    float4 xv = *(const float4*)(X + base);
    float4 yv = *(const float4*)(Y + base);
    float4 v = make_float4(xv.x+yv.x, xv.y+yv.y, xv.z+yv.z, xv.w+yv.w);

    float s = v.x+v.y+v.z+v.w;
    float ss = v.x*v.x+v.y*v.y+v.z*v.z+v.w*v.w;
#pragma unroll
    for (int o = 16; o > 0; o >>= 1) {
        s  += __shfl_xor_sync(0xffffffffu, s, o);
        ss += __shfl_xor_sync(0xffffffffu, ss, o);
    }
    __shared__ float rs[8], rss[8];
    const int w = tid >> 5, lane = tid & 31;
    if (lane == 0) { rs[w] = s; rss[w] = ss; }
    __syncthreads();
    if (tid == 0) {
        float S = 0.f, SS = 0.f;
#pragma unroll
        for (int i = 0; i < 8; i++) { S += rs[i]; SS += rss[i]; }
        rs[0] = S; rss[0] = SS;
    }
    __syncthreads();
    const float mean = rs[0] * (1.f / Dq);
    const float var  = rss[0] * (1.f / Dq) - mean * mean;
    const float rstd = rsqrtf(var + 1e-6f);

    float4 a4 = *(const float4*)(Aw + tid * 4);
    float4 b4 = *(const float4*)(Bw + tid * 4);
    float4 o4;
    o4.x = a4.x * (v.x - mean) * rstd + b4.x;
    o4.y = a4.y * (v.y - mean) * rstd + b4.y;
    o4.z = a4.z * (v.z - mean) * rstd + b4.z;
    o4.w = a4.w * (v.w - mean) * rstd + b4.w;
    *(float4*)(out + base) = o4;
    if (oh) {
        *(__half2*)(oh+base)   = __floats2half2_rn(o4.x, o4.y);
        *(__half2*)(oh+base+2) = __floats2half2_rn(o4.z, o4.w);
    }
}

// ---------------- kernel_launch ----------------
extern "C" void kernel_launch(void* const* d_in, const int* in_sizes, int n_in,
                              void* d_out, int out_size)
{
    const float* x   = (const float*)d_in[0];
    const int* mask  = (const int*)d_in[1];
    const float* wq  = (const float*)d_in[2];
    const float* bq  = (const float*)d_in[3];
    const float* wk  = (const float*)d_in[4];
    const float* bk  = (const float*)d_in[5];
    const float* wv  = (const float*)d_in[6];
    const float* bv  = (const float*)d_in[7];
    const float* wo  = (const float*)d_in[8];
    const float* bo  = (const float*)d_in[9];
    const float* l1a = (const float*)d_in[10];
    const float* l1b = (const float*)d_in[11];
    const float* l2a = (const float*)d_in[12];
    const float* l2b = (const float*)d_in[13];
    const float* w1  = (const float*)d_in[14];
    const float* b1  = (const float*)d_in[15];
    const float* w2  = (const float*)d_in[16];
    const float* b2  = (const float*)d_in[17];
    float* out = (float*)d_out;

    float *tmp, *x1, *bcat;
    h16 *qkv,*xh,*ah,*x1h,*fh,*wcat,*woh,*w1h,*w2h;
    cudaGetSymbolAddress((void**)&tmp, g_tmp);
    cudaGetSymbolAddress((void**)&x1, g_x1);
    cudaGetSymbolAddress((void**)&qkv, g_qkv);
    cudaGetSymbolAddress((void**)&xh, g_xh);
    cudaGetSymbolAddress((void**)&ah, g_ah);
    cudaGetSymbolAddress((void**)&x1h, g_x1h);
    cudaGetSymbolAddress((void**)&fh, g_fh);
    cudaGetSymbolAddress((void**)&wcat, g_wcat);
    cudaGetSymbolAddress((void**)&bcat, g_bcat);
    cudaGetSymbolAddress((void**)&woh, g_woh);
    cudaGetSymbolAddress((void**)&w1h, g_w1h);
    cudaGetSymbolAddress((void**)&w2h, g_w2h);

    static int inited = 0;
    static cudaStream_t s1, s3;
    static cudaEvent_t eFork, eK, eW;
    if (!inited) {
        cudaFuncSetAttribute(hgemm, cudaFuncAttributeMaxDynamicSharedMemorySize, SMEM_REQ);
        cudaStreamCreateWithFlags(&s1, cudaStreamNonBlocking);
        cudaStreamCreateWithFlags(&s3, cudaStreamNonBlocking);
        cudaEventCreateWithFlags(&eFork, cudaEventDisableTiming);
        cudaEventCreateWithFlags(&eK,    cudaEventDisableTiming);
        cudaEventCreateWithFlags(&eW,    cudaEventDisableTiming);
        inited = 1;
    }

    const dim3 gQKV(NQKV / BN, MROWS / BM);  // (12, 64)
    const dim3 gD(Dq / BN, MROWS / BM);      // (4, 64)
    const dim3 gF(DFFq / BN, MROWS / BM);    // (16, 64)

    cudaEventRecord(eFork, 0);
    cudaStreamWaitEvent(s1, eFork, 0);
    cudaStreamWaitEvent(s3, eFork, 0);

    // s1: QKV weight prep
    bcat_kernel<<<12, 256, 0, s1>>>(bq, bk, bv, bcat);
    ttrans_kernel<<<dim3(Dq/32, Dq/32), 256, 0, s1>>>(wq, wcat, Dq, Dq);
    ttrans_kernel<<<dim3(Dq/32, Dq/32), 256, 0, s1>>>(wk, wcat + (size_t)1024 * Dq, Dq, Dq);
    ttrans_kernel<<<dim3(Dq/32, Dq/32), 256, 0, s1>>>(wv, wcat + (size_t)2048 * Dq, Dq, Dq);
    cudaEventRecord(eK, s1);

    // s3: tail weights
    ttrans_kernel<<<dim3(Dq/32, Dq/32), 256, 0, s3>>>(wo, woh, Dq, Dq);
    ttrans_kernel<<<dim3(DFFq/32, Dq/32), 256, 0, s3>>>(w1, w1h, Dq, DFFq);
    ttrans_kernel<<<dim3(Dq/32, DFFq/32), 256, 0, s3>>>(w2, w2h, DFFq, Dq);
    cudaEventRecord(eW, s3);

    // default: activations
    vround_kernel<<<MROWS * Dq / 1024, 256>>>(x, xh, MROWS * Dq);
    cudaStreamWaitEvent(0, eK, 0);
    hgemm<<<gQKV, 256, SMEM_REQ>>>(xh, wcat, bcat, nullptr, qkv, MROWS, NQKV, Dq, 0);

    attention_hmma<<<dim3(Sq/128, Hq, Bq), 256>>>(qkv, mask, ah);

    cudaStreamWaitEvent(0, eW, 0);
    hgemm<<<gD, 256, SMEM_REQ>>>(ah, woh, bo, tmp, nullptr, MROWS, Dq, Dq, 0);
    residual_ln<<<MROWS, 256>>>(x, tmp, l1a, l1b, x1, x1h);

    hgemm<<<gF, 256, SMEM_REQ>>>(x1h, w1h, b1, nullptr, fh, MROWS, DFFq, Dq, 1);
    hgemm<<<gD, 256, SMEM_REQ>>>(fh, w2h, b2, tmp, nullptr, MROWS, Dq, DFFq, 0);
    residual_ln<<<MROWS, 256>>>(x1, tmp, l2a, l2b, out, nullptr);
}